// round 9
// baseline (speedup 1.0000x reference)
#include <cuda_runtime.h>
#include <cuda_bf16.h>

// Problem constants (fixed by the dataset)
#define Bn 4
#define Nn 50000
#define Dn 256
#define En 800000
#define NPTS (Bn * Nn)   // 200000
#define MAXDEG 96        // Poisson(32): P(deg>96) ~ 1e-18 over 50k nodes

// XPBD state, batch-interleaved: g_x[buf][4*n + b] = float4(x,y,z,pad).
// The 4 batches of a node are 64B contiguous.
__device__ float4 g_x[2][NPTS];

// Fixed-slot incidence table: node n owns g_slot[n*MAXDEG .. n*MAXDEG+deg).
// entry = {4*neighbor (pre-scaled float4 index), bitcast(L0)}. Rows padded to
// a multiple of 4 with self-edges (zero contribution).
__device__ int  g_cnt[Nn];
__device__ int2 g_slot[Nn * MAXDEG];   // 38.4 MB

// ---------------------------------------------------------------------------
// Stage 1: x_pred = keypoints + tau * (hand_tokens @ head_w + head_b)
// THREAD per point: each thread reads its own 1KB row with sequential
// LDG.128 (warp = 32 consecutive rows = fully-consumed contiguous 32KB).
// Weights live in smem but every lane reads the SAME address (lanes differ in
// point, not column) -> pure broadcast, conflict-free. No shuffles, no lane-0
// serialization: issue cost ~33 warp-instr/point << DRAM floor.
// ---------------------------------------------------------------------------
__global__ __launch_bounds__(256) void predict_kernel(
    const float* __restrict__ kp, const float* __restrict__ ts,
    const float* __restrict__ ht, const float* __restrict__ hw,
    const float* __restrict__ hb)
{
    __shared__ float4 sw4[Dn * 3 / 4];   // 192 float4 = 768 weights
    int tid = threadIdx.x;
    if (tid < 192) sw4[tid] = reinterpret_cast<const float4*>(hw)[tid];
    __syncthreads();

    int p = blockIdx.x * 256 + tid;
    if (p >= NPTS) return;

    const float4* h = reinterpret_cast<const float4*>(ht) + (size_t)p * 64;

    float ax = 0.f, ay = 0.f, az = 0.f;   // even chunks
    float bx = 0.f, by = 0.f, bz = 0.f;   // odd chunks (ILP)

#pragma unroll 1
    for (int i0 = 0; i0 < 64; i0 += 8) {
        float4 v[8];
#pragma unroll
        for (int j = 0; j < 8; j++) v[j] = __ldg(&h[i0 + j]);   // 8 in flight
#pragma unroll
        for (int j = 0; j < 8; j++) {
            int c = 3 * (i0 + j);
            float4 w0 = sw4[c + 0];   // broadcast LDS (all lanes same addr)
            float4 w1 = sw4[c + 1];
            float4 w2 = sw4[c + 2];
            if ((j & 1) == 0) {
                ax = fmaf(v[j].x, w0.x, ax); ay = fmaf(v[j].x, w0.y, ay); az = fmaf(v[j].x, w0.z, az);
                ax = fmaf(v[j].y, w0.w, ax); ay = fmaf(v[j].y, w1.x, ay); az = fmaf(v[j].y, w1.y, az);
                ax = fmaf(v[j].z, w1.z, ax); ay = fmaf(v[j].z, w1.w, ay); az = fmaf(v[j].z, w2.x, az);
                ax = fmaf(v[j].w, w2.y, ax); ay = fmaf(v[j].w, w2.z, ay); az = fmaf(v[j].w, w2.w, az);
            } else {
                bx = fmaf(v[j].x, w0.x, bx); by = fmaf(v[j].x, w0.y, by); bz = fmaf(v[j].x, w0.z, bz);
                bx = fmaf(v[j].y, w0.w, bx); by = fmaf(v[j].y, w1.x, by); bz = fmaf(v[j].y, w1.y, bz);
                bx = fmaf(v[j].z, w1.z, bx); by = fmaf(v[j].z, w1.w, by); bz = fmaf(v[j].z, w2.x, bz);
                bx = fmaf(v[j].w, w2.y, bx); by = fmaf(v[j].w, w2.z, by); bz = fmaf(v[j].w, w2.w, bz);
            }
        }
    }
    ax += bx; ay += by; az += bz;

    int b = p / Nn, n = p - b * Nn;
    float tau = fmaxf(1.0f - __ldg(&ts[b]), 0.001f);
    float kx = __ldg(&kp[(size_t)p * 3 + 0]);
    float ky = __ldg(&kp[(size_t)p * 3 + 1]);
    float kz = __ldg(&kp[(size_t)p * 3 + 2]);
    g_x[0][4 * n + b] = make_float4(fmaf(tau, ax + __ldg(&hb[0]), kx),
                                    fmaf(tau, ay + __ldg(&hb[1]), ky),
                                    fmaf(tau, az + __ldg(&hb[2]), kz), 0.0f);
}

// ---------------------------------------------------------------------------
// Incidence build (side stream, hidden under predict).
// ---------------------------------------------------------------------------
__global__ __launch_bounds__(256) void zero_kernel()
{
    int i = blockIdx.x * blockDim.x + threadIdx.x;
    if (i < Nn) g_cnt[i] = 0;
}

__global__ __launch_bounds__(256) void fill_kernel(
    const int* __restrict__ ei, const float* __restrict__ rest)
{
    int e = blockIdx.x * blockDim.x + threadIdx.x;
    if (e >= En) return;
    int s  = __ldg(&ei[e]);
    int d  = __ldg(&ei[En + e]);
    int L0 = __float_as_int(__ldg(&rest[e]));
    int cs = atomicAdd(&g_cnt[s], 1);
    if (cs < MAXDEG) g_slot[s * MAXDEG + cs] = make_int2(4 * d, L0);
    int cd = atomicAdd(&g_cnt[d], 1);
    if (cd < MAXDEG) g_slot[d * MAXDEG + cd] = make_int2(4 * s, L0);
}

__global__ __launch_bounds__(256) void pad_kernel()
{
    int n = blockIdx.x * blockDim.x + threadIdx.x;
    if (n >= Nn) return;
    int c = min(g_cnt[n], MAXDEG);
    int p = (c + 3) & ~3;                    // pad to multiple of 4
    int2 self = make_int2(4 * n, __float_as_int(1.0f));  // zero contribution
    for (int k = c; k < p; k++) g_slot[n * MAXDEG + k] = self;
    g_cnt[n] = p;
}

// ---------------------------------------------------------------------------
// One XPBD Jacobi iteration. TWO threads per (node, batch): thread half h
// walks 4-edge groups k = 4h, 4h+8, ... (halving the per-thread dependent
// chain), entries for the next group prefetched before this group's gathers.
// Halves combined with shfl_xor(4); h==0 writes. Thread layout t = 8n + 4h + b
// keeps the 4 batch-siblings' gathers in one contiguous 64B segment.
// ---------------------------------------------------------------------------
__global__ __launch_bounds__(128) void node_kernel(int from, int to)
{
    int t = blockIdx.x * blockDim.x + threadIdx.x;   // exact: 3125*128
    int n = t >> 3;
    int b = t & 3;
    int h = (t >> 2) & 1;

    const float4* __restrict__ xin = g_x[from];
    float4 own = __ldg(&xin[4 * n + b]);

    int deg = __ldg(&g_cnt[n]);              // multiple of 4
    const int2* row = &g_slot[n * MAXDEG];

    float ax = 0.f, ay = 0.f, az = 0.f;

    int k = 4 * h;
    if (k < deg) {
        int4 ea = __ldg(reinterpret_cast<const int4*>(row + k));
        int4 eb = __ldg(reinterpret_cast<const int4*>(row + k + 2));
        while (true) {
            int kn = k + 8;
            int4 na, nb;
            bool more = (kn < deg);
            if (more) {                      // prefetch next group's entries
                na = __ldg(reinterpret_cast<const int4*>(row + kn));
                nb = __ldg(reinterpret_cast<const int4*>(row + kn + 2));
            }
            int   js[4]  = {ea.x, ea.z, eb.x, eb.z};    // already 4*j
            float L0s[4] = {__int_as_float(ea.y), __int_as_float(ea.w),
                            __int_as_float(eb.y), __int_as_float(eb.w)};
            float4 xj[4];
#pragma unroll
            for (int i = 0; i < 4; i++)
                xj[i] = __ldg(&xin[js[i] + b]);
#pragma unroll
            for (int i = 0; i < 4; i++) {
                float dx = own.x - xj[i].x;
                float dy = own.y - xj[i].y;
                float dz = own.z - xj[i].z;
                float d2 = fmaf(dx, dx, fmaf(dy, dy, dz * dz));
                float r  = rsqrtf(fmaxf(d2, 1e-24f));
                float f  = fmaf(L0s[i], r, -1.0f);      // 2x true scale
                ax += fminf(fmaxf(f * dx, -0.3f), 0.3f);
                ay += fminf(fmaxf(f * dy, -0.3f), 0.3f);
                az += fminf(fmaxf(f * dz, -0.3f), 0.3f);
            }
            if (!more) break;
            ea = na; eb = nb; k = kn;
        }
    }

    // combine the two halves (partner differs only in h -> lane xor 4)
    ax += __shfl_xor_sync(0xffffffffu, ax, 4);
    ay += __shfl_xor_sync(0xffffffffu, ay, 4);
    az += __shfl_xor_sync(0xffffffffu, az, 4);

    if (h == 0)
        g_x[to][4 * n + b] = make_float4(fmaf(0.5f, ax, own.x),
                                         fmaf(0.5f, ay, own.y),
                                         fmaf(0.5f, az, own.z), 0.0f);
}

// ---------------------------------------------------------------------------
// Stage 3: v_eff = (x_corrected - keypoints) / tau
// ---------------------------------------------------------------------------
__global__ __launch_bounds__(256) void final_kernel(
    const float* __restrict__ kp, const float* __restrict__ ts,
    int buf, float* __restrict__ out)
{
    int n = blockIdx.x * blockDim.x + threadIdx.x;
    if (n >= Nn) return;
    const float4* x = g_x[buf];
#pragma unroll
    for (int b = 0; b < Bn; b++) {
        float4 p = x[4 * n + b];
        float inv_tau = 1.0f / fmaxf(1.0f - __ldg(&ts[b]), 0.001f);
        size_t o = (size_t)(b * Nn + n) * 3;
        out[o + 0] = (p.x - __ldg(&kp[o + 0])) * inv_tau;
        out[o + 1] = (p.y - __ldg(&kp[o + 1])) * inv_tau;
        out[o + 2] = (p.z - __ldg(&kp[o + 2])) * inv_tau;
    }
}

extern "C" void kernel_launch(void* const* d_in, const int* in_sizes, int n_in,
                              void* d_out, int out_size)
{
    const float* kp   = (const float*)d_in[0];  // keypoints   (B,N,3)
    const float* ts   = (const float*)d_in[1];  // timesteps   (B,)
    const float* ht   = (const float*)d_in[2];  // hand_tokens (B,N,D)
    const float* hw   = (const float*)d_in[3];  // head_w      (D,3)
    const float* hb   = (const float*)d_in[4];  // head_b      (3,)
    const int*   ei   = (const int*)  d_in[5];  // edge_index  (2,E)
    const float* rest = (const float*)d_in[6];  // rest_lengths(E,)
    float*       out  = (float*)d_out;          // v_eff       (B,N,3)

    (void)in_sizes; (void)n_in; (void)out_size;

    // Side stream + fork/join events, created once on the first (uncaptured)
    // correctness call. Host-side objects only.
    static cudaStream_t side = nullptr;
    static cudaEvent_t  ev_fork = nullptr, ev_join = nullptr;
    if (side == nullptr) {
        cudaStreamCreateWithFlags(&side, cudaStreamNonBlocking);
        cudaEventCreateWithFlags(&ev_fork, cudaEventDisableTiming);
        cudaEventCreateWithFlags(&ev_join, cudaEventDisableTiming);
    }

    const int nb_nodes = (Nn + 255) / 256;
    const int nb_edges = (En + 255) / 256;
    const int nb_pred  = (NPTS + 255) / 256;
    const int nb_node2 = (2 * NPTS) / 128;     // 3125, exact

    // Fork: incidence build on side stream, concurrent with predict.
    cudaEventRecord(ev_fork, 0);
    cudaStreamWaitEvent(side, ev_fork, 0);
    zero_kernel<<<nb_nodes, 256, 0, side>>>();
    fill_kernel<<<nb_edges, 256, 0, side>>>(ei, rest);
    pad_kernel <<<nb_nodes, 256, 0, side>>>();

    // Stage 1 on the main stream, overlapping the build
    predict_kernel<<<nb_pred, 256>>>(kp, ts, ht, hw, hb);

    // Join
    cudaEventRecord(ev_join, side);
    cudaStreamWaitEvent(0, ev_join, 0);

    // Stage 2: 4 Jacobi XPBD iterations, node-centric, ping-pong
    node_kernel<<<nb_node2, 128>>>(0, 1);
    node_kernel<<<nb_node2, 128>>>(1, 0);
    node_kernel<<<nb_node2, 128>>>(0, 1);
    node_kernel<<<nb_node2, 128>>>(1, 0);

    // Stage 3: velocity output from buffer 0
    final_kernel<<<nb_nodes, 256>>>(kp, ts, 0, out);
}

// round 10
// speedup vs baseline: 1.1885x; 1.1885x over previous
#include <cuda_runtime.h>
#include <cuda_bf16.h>

// Problem constants (fixed by the dataset)
#define Bn 4
#define Nn 50000
#define Dn 256
#define En 800000
#define NPTS (Bn * Nn)   // 200000
#define MAXDEG 96        // Poisson(32): P(deg>96) ~ 1e-18 over 50k nodes

// XPBD state, batch-interleaved: g_x[buf][4*n + b] = float4(x,y,z,pad).
// The 4 batches of a node are 64B contiguous.
__device__ float4 g_x[2][NPTS];

// Fixed-slot incidence table: node n owns g_slot[n*MAXDEG .. n*MAXDEG+deg).
// entry = {4*neighbor (pre-scaled float4 index), bitcast(L0)}. Rows padded to
// a multiple of 4 with self-edges (zero contribution).
__device__ int  g_cnt[Nn];
__device__ int2 g_slot[Nn * MAXDEG];   // 38.4 MB

// ---------------------------------------------------------------------------
// Stage 1: x_pred = keypoints + tau * (hand_tokens @ head_w + head_b)
// Warp per point: two coalesced LDG.128 (lane l owns cols 4l..4l+3 and
// 128+4l..+3), weights from CONFLICT-FREE padded smem: lane l's 24 weights
// live at sw[25l .. 25l+23] (stride 25, gcd(25,32)=1 -> 1 phase per LDS,
// vs the 4-way-conflict 12-stride layout). 32 regs, high occupancy.
// ---------------------------------------------------------------------------
__global__ __launch_bounds__(256) void predict_kernel(
    const float* __restrict__ kp, const float* __restrict__ ts,
    const float* __restrict__ ht, const float* __restrict__ hw,
    const float* __restrict__ hb)
{
    __shared__ float sw[25 * 32];   // 800 floats, lane-padded layout
    __shared__ float sb[3];
    int tid = threadIdx.x;
    for (int idx = tid; idx < Dn * 3; idx += 256) {
        int r = idx / 3, c = idx - 3 * r;
        int pos = (r < 128) ? (25 * (r >> 2) + 3 * (r & 3) + c)
                            : (25 * ((r - 128) >> 2) + 12 + 3 * ((r - 128) & 3) + c);
        sw[pos] = hw[idx];
    }
    if (tid < 3) sb[tid] = hb[tid];
    __syncthreads();

    int warp = tid >> 5, lane = tid & 31;
    int p = blockIdx.x * 8 + warp;   // grid = NPTS/8 exactly
    if (p >= NPTS) return;

    const float4* h = reinterpret_cast<const float4*>(ht) + (size_t)p * 64;
    float4 h0 = __ldg(&h[lane]);        // cols 4l..4l+3
    float4 h1 = __ldg(&h[32 + lane]);   // cols 128+4l..+3

    const float* wl = &sw[25 * lane];
    float hv[8] = {h0.x, h0.y, h0.z, h0.w, h1.x, h1.y, h1.z, h1.w};
    float a0 = 0.f, a1 = 0.f, a2 = 0.f;
#pragma unroll
    for (int i = 0; i < 8; i++) {
        a0 = fmaf(hv[i], wl[3 * i + 0], a0);
        a1 = fmaf(hv[i], wl[3 * i + 1], a1);
        a2 = fmaf(hv[i], wl[3 * i + 2], a2);
    }
#pragma unroll
    for (int o = 16; o >= 1; o >>= 1) {
        a0 += __shfl_xor_sync(0xffffffffu, a0, o);
        a1 += __shfl_xor_sync(0xffffffffu, a1, o);
        a2 += __shfl_xor_sync(0xffffffffu, a2, o);
    }
    if (lane == 0) {
        int b = p / Nn, n = p - b * Nn;
        float tau = fmaxf(1.0f - __ldg(&ts[b]), 0.001f);
        float kx = __ldg(&kp[(size_t)p * 3 + 0]);
        float ky = __ldg(&kp[(size_t)p * 3 + 1]);
        float kz = __ldg(&kp[(size_t)p * 3 + 2]);
        g_x[0][4 * n + b] = make_float4(fmaf(tau, a0 + sb[0], kx),
                                        fmaf(tau, a1 + sb[1], ky),
                                        fmaf(tau, a2 + sb[2], kz), 0.0f);
    }
}

// ---------------------------------------------------------------------------
// Incidence build (side stream, hidden under predict).
// ---------------------------------------------------------------------------
__global__ __launch_bounds__(256) void zero_kernel()
{
    int i = blockIdx.x * blockDim.x + threadIdx.x;
    if (i < Nn) g_cnt[i] = 0;
}

__global__ __launch_bounds__(256) void fill_kernel(
    const int* __restrict__ ei, const float* __restrict__ rest)
{
    int e = blockIdx.x * blockDim.x + threadIdx.x;
    if (e >= En) return;
    int s  = __ldg(&ei[e]);
    int d  = __ldg(&ei[En + e]);
    int L0 = __float_as_int(__ldg(&rest[e]));
    int cs = atomicAdd(&g_cnt[s], 1);
    if (cs < MAXDEG) g_slot[s * MAXDEG + cs] = make_int2(4 * d, L0);
    int cd = atomicAdd(&g_cnt[d], 1);
    if (cd < MAXDEG) g_slot[d * MAXDEG + cd] = make_int2(4 * s, L0);
}

__global__ __launch_bounds__(256) void pad_kernel()
{
    int n = blockIdx.x * blockDim.x + threadIdx.x;
    if (n >= Nn) return;
    int c = min(g_cnt[n], MAXDEG);
    int p = (c + 3) & ~3;                    // pad to multiple of 4
    int2 self = make_int2(4 * n, __float_as_int(1.0f));  // zero contribution
    for (int k = c; k < p; k++) g_slot[n * MAXDEG + k] = self;
    g_cnt[n] = p;
}

// ---------------------------------------------------------------------------
// One XPBD Jacobi iteration. FOUR threads per (node, batch): quarter h walks
// 4-edge groups k = 4h, 4h+16, ... (dependent chain ~2 rounds/thread; MLP
// comes from 800k threads). Layout t = 16n + 4h + b keeps the 4 batch-
// siblings' gathers in one contiguous 64B segment and h-copies' loads
// L1-broadcast. Quarters combined with shfl_xor(4) + shfl_xor(8); h==0 writes.
// Grid exact: 800000 = 6250 x 128.
// ---------------------------------------------------------------------------
__global__ __launch_bounds__(128) void node_kernel(int from, int to)
{
    int t = blockIdx.x * 128 + threadIdx.x;
    int n = t >> 4;
    int b = t & 3;
    int h = (t >> 2) & 3;

    const float4* __restrict__ xin = g_x[from];
    float4 own = __ldg(&xin[4 * n + b]);

    int deg = __ldg(&g_cnt[n]);              // multiple of 4
    const int2* row = &g_slot[n * MAXDEG];

    float ax = 0.f, ay = 0.f, az = 0.f;

#pragma unroll 2
    for (int k = 4 * h; k < deg; k += 16) {
        int4 ea = __ldg(reinterpret_cast<const int4*>(row + k));
        int4 eb = __ldg(reinterpret_cast<const int4*>(row + k + 2));
        int   js[4]  = {ea.x, ea.z, eb.x, eb.z};    // already 4*j
        float L0s[4] = {__int_as_float(ea.y), __int_as_float(ea.w),
                        __int_as_float(eb.y), __int_as_float(eb.w)};
        float4 xj[4];
#pragma unroll
        for (int i = 0; i < 4; i++)
            xj[i] = __ldg(&xin[js[i] + b]);
#pragma unroll
        for (int i = 0; i < 4; i++) {
            float dx = own.x - xj[i].x;
            float dy = own.y - xj[i].y;
            float dz = own.z - xj[i].z;
            float d2 = fmaf(dx, dx, fmaf(dy, dy, dz * dz));
            float r  = rsqrtf(fmaxf(d2, 1e-24f));
            float f  = fmaf(L0s[i], r, -1.0f);      // 2x true scale
            ax += fminf(fmaxf(f * dx, -0.3f), 0.3f);
            ay += fminf(fmaxf(f * dy, -0.3f), 0.3f);
            az += fminf(fmaxf(f * dz, -0.3f), 0.3f);
        }
    }

    // combine the four quarters (partners differ in bits 2..3 of t)
    ax += __shfl_xor_sync(0xffffffffu, ax, 4);
    ay += __shfl_xor_sync(0xffffffffu, ay, 4);
    az += __shfl_xor_sync(0xffffffffu, az, 4);
    ax += __shfl_xor_sync(0xffffffffu, ax, 8);
    ay += __shfl_xor_sync(0xffffffffu, ay, 8);
    az += __shfl_xor_sync(0xffffffffu, az, 8);

    if (h == 0)
        g_x[to][4 * n + b] = make_float4(fmaf(0.5f, ax, own.x),
                                         fmaf(0.5f, ay, own.y),
                                         fmaf(0.5f, az, own.z), 0.0f);
}

// ---------------------------------------------------------------------------
// Stage 3: v_eff = (x_corrected - keypoints) / tau
// ---------------------------------------------------------------------------
__global__ __launch_bounds__(256) void final_kernel(
    const float* __restrict__ kp, const float* __restrict__ ts,
    int buf, float* __restrict__ out)
{
    int n = blockIdx.x * blockDim.x + threadIdx.x;
    if (n >= Nn) return;
    const float4* x = g_x[buf];
#pragma unroll
    for (int b = 0; b < Bn; b++) {
        float4 p = x[4 * n + b];
        float inv_tau = 1.0f / fmaxf(1.0f - __ldg(&ts[b]), 0.001f);
        size_t o = (size_t)(b * Nn + n) * 3;
        out[o + 0] = (p.x - __ldg(&kp[o + 0])) * inv_tau;
        out[o + 1] = (p.y - __ldg(&kp[o + 1])) * inv_tau;
        out[o + 2] = (p.z - __ldg(&kp[o + 2])) * inv_tau;
    }
}

extern "C" void kernel_launch(void* const* d_in, const int* in_sizes, int n_in,
                              void* d_out, int out_size)
{
    const float* kp   = (const float*)d_in[0];  // keypoints   (B,N,3)
    const float* ts   = (const float*)d_in[1];  // timesteps   (B,)
    const float* ht   = (const float*)d_in[2];  // hand_tokens (B,N,D)
    const float* hw   = (const float*)d_in[3];  // head_w      (D,3)
    const float* hb   = (const float*)d_in[4];  // head_b      (3,)
    const int*   ei   = (const int*)  d_in[5];  // edge_index  (2,E)
    const float* rest = (const float*)d_in[6];  // rest_lengths(E,)
    float*       out  = (float*)d_out;          // v_eff       (B,N,3)

    (void)in_sizes; (void)n_in; (void)out_size;

    // Side stream + fork/join events, created once on the first (uncaptured)
    // correctness call. Host-side objects only.
    static cudaStream_t side = nullptr;
    static cudaEvent_t  ev_fork = nullptr, ev_join = nullptr;
    if (side == nullptr) {
        cudaStreamCreateWithFlags(&side, cudaStreamNonBlocking);
        cudaEventCreateWithFlags(&ev_fork, cudaEventDisableTiming);
        cudaEventCreateWithFlags(&ev_join, cudaEventDisableTiming);
    }

    const int nb_nodes = (Nn + 255) / 256;
    const int nb_edges = (En + 255) / 256;
    const int nb_node4 = (4 * NPTS) / 128;     // 6250, exact

    // Fork: incidence build on side stream, concurrent with predict.
    cudaEventRecord(ev_fork, 0);
    cudaStreamWaitEvent(side, ev_fork, 0);
    zero_kernel<<<nb_nodes, 256, 0, side>>>();
    fill_kernel<<<nb_edges, 256, 0, side>>>(ei, rest);
    pad_kernel <<<nb_nodes, 256, 0, side>>>();

    // Stage 1 on the main stream, overlapping the build
    predict_kernel<<<NPTS / 8, 256>>>(kp, ts, ht, hw, hb);

    // Join
    cudaEventRecord(ev_join, side);
    cudaStreamWaitEvent(0, ev_join, 0);

    // Stage 2: 4 Jacobi XPBD iterations, node-centric, ping-pong
    node_kernel<<<nb_node4, 128>>>(0, 1);
    node_kernel<<<nb_node4, 128>>>(1, 0);
    node_kernel<<<nb_node4, 128>>>(0, 1);
    node_kernel<<<nb_node4, 128>>>(1, 0);

    // Stage 3: velocity output from buffer 0
    final_kernel<<<nb_nodes, 256>>>(kp, ts, 0, out);
}